// round 3
// baseline (speedup 1.0000x reference)
#include <cuda_runtime.h>
#include <cstdint>
#include <math.h>

// Problem constants
#define NB   32
#define NS   2048
#define ND   1024
#define BSR  65536      // NB*NS rows
#define T_M  128
#define T_N  128
#define T_K  32
#define NKT  32         // ND / T_K
#define NT_N 8          // 1024 / 128 N-tiles

// Device scratch (no dynamic allocation allowed)
__device__ float g_qw[NB * ND];
__device__ float g_scores_part[NT_N][BSR];
__device__ float g_ctx_part[8][NB * ND];

// ---------------- smem layout (floats) for gemm kernel ----------------
// A bufs: 2 x 128 x 36, B bufs: 2 x 128 x 36, qw 128, va 128, scores 2x128
#define SA_STRIDE 36
#define OFF_A  0
#define OFF_B  9216
#define OFF_QW 18432
#define OFF_VA 18560
#define OFF_SC 18688
#define SMEM_FLOATS 18944
#define SMEM_BYTES (SMEM_FLOATS * 4)

__device__ __forceinline__ uint32_t f2tf32(float x) {
    uint32_t u;
    asm("cvt.rna.tf32.f32 %0, %1;" : "=r"(u) : "f"(x));
    return u;
}

__device__ __forceinline__ void mma_tf32(float* d, const uint32_t* a, const uint32_t* b) {
    asm volatile(
        "mma.sync.aligned.m16n8k8.row.col.f32.tf32.tf32.f32 "
        "{%0,%1,%2,%3}, {%4,%5,%6,%7}, {%8,%9}, {%0,%1,%2,%3};"
        : "+f"(d[0]), "+f"(d[1]), "+f"(d[2]), "+f"(d[3])
        : "r"(a[0]), "r"(a[1]), "r"(a[2]), "r"(a[3]), "r"(b[0]), "r"(b[1]));
}

// ---------------- Kernel 0: qW[b,n] = q[b] . Wa_w[n,:] + Wa_b[n] + Ua_b[n] ----------------
__global__ void qw_kernel(const float* __restrict__ query, const float* __restrict__ Wa_w,
                          const float* __restrict__ Wa_b, const float* __restrict__ Ua_b) {
    int b = blockIdx.x;
    int tid = threadIdx.x;                    // 128 threads
    int n = blockIdx.y * 128 + tid;
    __shared__ float4 qs[256];                // q[b] as 1024 floats
    for (int i = tid; i < 256; i += 128) {
        int k = i * 4;
        // q = concat(query[b,1,:], query[b,3,:]); query is (B,4,512)
        const float* src = (k < 512) ? (query + (size_t)b * 2048 + 512 + k)
                                     : (query + (size_t)b * 2048 + 1024 + k);
        qs[i] = *(const float4*)src;
    }
    __syncthreads();
    const float4* wr = (const float4*)(Wa_w + (size_t)n * ND);
    float acc = 0.f;
    #pragma unroll 8
    for (int i = 0; i < 256; i++) {
        float4 a = qs[i], w = wr[i];
        acc += a.x * w.x + a.y * w.y + a.z * w.z + a.w * w.w;
    }
    g_qw[b * ND + n] = acc + Wa_b[n] + Ua_b[n];
}

// ---------------- Kernel 1: tf32 mma.sync GEMM + fused tanh/Va epilogue ----------------
__global__ void __launch_bounds__(256, 2)
gemm_score_kernel(const float* __restrict__ keys, const float* __restrict__ Ua_w,
                  const float* __restrict__ Va_w) {
    extern __shared__ float sm[];
    float* As = sm + OFF_A;
    float* Bs = sm + OFF_B;
    float* qw_s = sm + OFF_QW;
    float* va_s = sm + OFF_VA;
    float* sc_s = sm + OFF_SC;

    const int tid = threadIdx.x;              // 256 threads, 8 warps
    const int wid = tid >> 5;
    const int lane = tid & 31;
    const int r = lane >> 2;                  // 0..7
    const int c = lane & 3;                   // 0..3
    const int wm = wid & 3;                   // 4 warps along M (32 rows each)
    const int wn = wid >> 2;                  // 2 warps along N (64 cols each)

    const int nt = blockIdx.x;                // N-tile (fast dim -> A reuse in L2)
    const int n0 = nt * T_N;
    const int m0 = blockIdx.y * T_M;
    const int b  = blockIdx.y >> 4;           // 16 M-tiles per batch (S=2048/128)

    for (int j = tid; j < T_N; j += 256) {
        qw_s[j] = g_qw[b * ND + n0 + j];
        va_s[j] = Va_w[n0 + j];
    }

    // async tile loader: 1024 16B-chunks per matrix, 256 threads => 4 each
    auto load_tile = [&](int kt, int p) {
        const float* asrc = keys + (size_t)m0 * ND + (size_t)kt * T_K;
        const float* bsrc = Ua_w + (size_t)n0 * ND + (size_t)kt * T_K;
        float* ad = As + p * 4608;
        float* bd = Bs + p * 4608;
        #pragma unroll
        for (int i = 0; i < 4; i++) {
            int c0 = tid + i * 256;
            int row = c0 >> 3, ch = c0 & 7;
            {
                uint32_t dst = (uint32_t)__cvta_generic_to_shared(ad + row * SA_STRIDE + ch * 4);
                const float* src = asrc + (size_t)row * ND + ch * 4;
                asm volatile("cp.async.cg.shared.global [%0], [%1], 16;" :: "r"(dst), "l"(src));
            }
            {
                uint32_t dst = (uint32_t)__cvta_generic_to_shared(bd + row * SA_STRIDE + ch * 4);
                const float* src = bsrc + (size_t)row * ND + ch * 4;
                asm volatile("cp.async.cg.shared.global [%0], [%1], 16;" :: "r"(dst), "l"(src));
            }
        }
        asm volatile("cp.async.commit_group;");
    };

    float acc[2][8][4];
    #pragma unroll
    for (int im = 0; im < 2; im++)
        #pragma unroll
        for (int in = 0; in < 8; in++)
            #pragma unroll
            for (int k = 0; k < 4; k++) acc[im][in][k] = 0.f;

    load_tile(0, 0);

    for (int kt = 0; kt < NKT; kt++) {
        const int p = kt & 1;
        if (kt + 1 < NKT) {
            load_tile(kt + 1, 1 - p);
            asm volatile("cp.async.wait_group 1;");
        } else {
            asm volatile("cp.async.wait_group 0;");
        }
        __syncthreads();

        const float* ap = As + p * 4608;
        const float* bp = Bs + p * 4608;
        #pragma unroll
        for (int ks = 0; ks < 4; ks++) {
            const int k0 = ks * 8;
            uint32_t afr[2][4];
            #pragma unroll
            for (int im = 0; im < 2; im++) {
                int row = wm * 32 + im * 16 + r;
                afr[im][0] = f2tf32(ap[row * SA_STRIDE + k0 + c]);
                afr[im][1] = f2tf32(ap[(row + 8) * SA_STRIDE + k0 + c]);
                afr[im][2] = f2tf32(ap[row * SA_STRIDE + k0 + c + 4]);
                afr[im][3] = f2tf32(ap[(row + 8) * SA_STRIDE + k0 + c + 4]);
            }
            uint32_t bfr[8][2];
            #pragma unroll
            for (int in = 0; in < 8; in++) {
                int n = wn * 64 + in * 8 + r;
                bfr[in][0] = f2tf32(bp[n * SA_STRIDE + k0 + c]);
                bfr[in][1] = f2tf32(bp[n * SA_STRIDE + k0 + c + 4]);
            }
            #pragma unroll
            for (int im = 0; im < 2; im++)
                #pragma unroll
                for (int in = 0; in < 8; in++)
                    mma_tf32(acc[im][in], afr[im], bfr[in]);
        }
        __syncthreads();   // before next load overwrites buffer p
    }

    // Epilogue: score_part[m] = sum_n Va[n] * tanh(acc[m][n] + qw[n]) over this CTA's 128 n
    float rowsum[2][2] = {{0.f, 0.f}, {0.f, 0.f}};
    #pragma unroll
    for (int im = 0; im < 2; im++) {
        #pragma unroll
        for (int in = 0; in < 8; in++) {
            int col0 = wn * 64 + in * 8 + 2 * c;
            float v0 = va_s[col0],     q0 = qw_s[col0];
            float v1 = va_s[col0 + 1], q1 = qw_s[col0 + 1];
            rowsum[im][0] += v0 * tanhf(acc[im][in][0] + q0) + v1 * tanhf(acc[im][in][1] + q1);
            rowsum[im][1] += v0 * tanhf(acc[im][in][2] + q0) + v1 * tanhf(acc[im][in][3] + q1);
        }
    }
    // reduce the 4 lanes sharing each row (lane^1, lane^2 stay in the quad)
    #pragma unroll
    for (int im = 0; im < 2; im++)
        #pragma unroll
        for (int h = 0; h < 2; h++) {
            float v = rowsum[im][h];
            v += __shfl_xor_sync(0xffffffffu, v, 1);
            v += __shfl_xor_sync(0xffffffffu, v, 2);
            rowsum[im][h] = v;
        }
    if (c == 0) {
        #pragma unroll
        for (int im = 0; im < 2; im++) {
            int rowb = wm * 32 + im * 16 + r;
            sc_s[wn * 128 + rowb] = rowsum[im][0];
            sc_s[wn * 128 + rowb + 8] = rowsum[im][1];
        }
    }
    __syncthreads();
    if (tid < 128) {
        g_scores_part[nt][m0 + tid] = sc_s[tid] + sc_s[128 + tid];
    }
}

// ---------------- Kernel 2: softmax over S per batch, writes weights output ----------------
__global__ void softmax_kernel(float* __restrict__ wts) {
    int b = blockIdx.x;
    int tid = threadIdx.x;                    // 256 threads
    __shared__ float red[8];
    float v[8];
    float mx = -1e30f;
    #pragma unroll
    for (int i = 0; i < 8; i++) {
        int s = tid + i * 256;
        float x = 0.f;
        #pragma unroll
        for (int t = 0; t < NT_N; t++) x += g_scores_part[t][b * NS + s];
        v[i] = x;
        mx = fmaxf(mx, x);
    }
    #pragma unroll
    for (int o = 16; o; o >>= 1) mx = fmaxf(mx, __shfl_xor_sync(0xffffffffu, mx, o));
    if ((tid & 31) == 0) red[tid >> 5] = mx;
    __syncthreads();
    float bm = red[0];
    #pragma unroll
    for (int i = 1; i < 8; i++) bm = fmaxf(bm, red[i]);
    __syncthreads();
    float sum = 0.f;
    #pragma unroll
    for (int i = 0; i < 8; i++) { v[i] = __expf(v[i] - bm); sum += v[i]; }
    #pragma unroll
    for (int o = 16; o; o >>= 1) sum += __shfl_xor_sync(0xffffffffu, sum, o);
    if ((tid & 31) == 0) red[tid >> 5] = sum;
    __syncthreads();
    float bs = 0.f;
    #pragma unroll
    for (int i = 0; i < 8; i++) bs += red[i];
    float inv = 1.0f / bs;
    #pragma unroll
    for (int i = 0; i < 8; i++) wts[b * NS + tid + i * 256] = v[i] * inv;
}

// ---------------- Kernel 3: context partials (s-split for bandwidth) ----------------
__global__ void ctx_part_kernel(const float* __restrict__ keys, const float* __restrict__ wts) {
    int b = blockIdx.x;
    int d = blockIdx.y * 128 + threadIdx.x;
    int z = blockIdx.z;
    int s0 = z * 256;
    __shared__ float ws[256];
    for (int i = threadIdx.x; i < 256; i += 128) ws[i] = wts[b * NS + s0 + i];
    __syncthreads();
    const float* kp = keys + ((size_t)(b * NS + s0)) * ND + d;
    float acc = 0.f;
    #pragma unroll 8
    for (int s = 0; s < 256; s++) acc += ws[s] * kp[(size_t)s * ND];
    g_ctx_part[z][b * ND + d] = acc;
}

// ---------------- Kernel 4: reduce context partials -> output ----------------
__global__ void ctx_reduce_kernel(float* __restrict__ ctx) {
    int b = blockIdx.x;
    int d = threadIdx.x;                      // 1024 threads
    float a = 0.f;
    #pragma unroll
    for (int z = 0; z < 8; z++) a += g_ctx_part[z][b * ND + d];
    ctx[b * ND + d] = a;
}

// ---------------- launch ----------------
extern "C" void kernel_launch(void* const* d_in, const int* in_sizes, int n_in,
                              void* d_out, int out_size) {
    const float* query = (const float*)d_in[0];
    const float* keys  = (const float*)d_in[1];
    const float* Wa_w  = (const float*)d_in[2];
    const float* Wa_b  = (const float*)d_in[3];
    const float* Ua_w  = (const float*)d_in[4];
    const float* Ua_b  = (const float*)d_in[5];
    const float* Va_w  = (const float*)d_in[6];
    // Va_b (d_in[7]) cancels in softmax; scores are not an output.

    float* out = (float*)d_out;
    float* ctx = out;                                  // (B,1,2H) = 32768 floats
    float* wts = (out_size >= NB * ND + NB * NS) ? out + NB * ND : out;  // (B,1,S)

    cudaFuncSetAttribute(gemm_score_kernel, cudaFuncAttributeMaxDynamicSharedMemorySize, SMEM_BYTES);

    qw_kernel<<<dim3(NB, 8), 128>>>(query, Wa_w, Wa_b, Ua_b);
    gemm_score_kernel<<<dim3(NT_N, BSR / T_M), 256, SMEM_BYTES>>>(keys, Ua_w, Va_w);
    softmax_kernel<<<NB, 256>>>(wts);
    ctx_part_kernel<<<dim3(NB, 8, 8), 128>>>(keys, wts);
    ctx_reduce_kernel<<<NB, 1024>>>(ctx);
}

// round 4
// speedup vs baseline: 1.0006x; 1.0006x over previous
#include <cuda_runtime.h>
#include <cstdint>
#include <math.h>

// Problem constants
#define NB   32
#define NS   2048
#define ND   1024
#define BSR  65536      // NB*NS rows
#define T_M  256
#define T_N  128
#define T_K  32
#define NKT  32         // ND / T_K
#define NT_N 8          // 1024 / 128 N-tiles

// Device scratch (no dynamic allocation allowed)
__device__ float g_qw[NB * ND];
__device__ float g_scores_part[NT_N][BSR];
__device__ float g_ctx_part[8][NB * ND];

// ---------------- smem layout (floats) for gemm kernel ----------------
#define SA_STRIDE 36
#define A_BUF  (T_M * SA_STRIDE)          // 9216
#define B_BUF  (T_N * SA_STRIDE)          // 4608
#define OFF_A  0
#define OFF_B  (2 * A_BUF)                // 18432
#define OFF_QW (OFF_B + 2 * B_BUF)        // 27648
#define OFF_VA (OFF_QW + 128)
#define OFF_SC (OFF_VA + 128)             // 512 floats
#define SMEM_FLOATS (OFF_SC + 512)        // 28416
#define SMEM_BYTES (SMEM_FLOATS * 4)      // 113664

__device__ __forceinline__ uint32_t f2tf32(float x) {
    uint32_t u;
    asm("cvt.rna.tf32.f32 %0, %1;" : "=r"(u) : "f"(x));
    return u;
}

__device__ __forceinline__ void mma_tf32(float* d, const uint32_t* a, const uint32_t* b) {
    asm volatile(
        "mma.sync.aligned.m16n8k8.row.col.f32.tf32.tf32.f32 "
        "{%0,%1,%2,%3}, {%4,%5,%6,%7}, {%8,%9}, {%0,%1,%2,%3};"
        : "+f"(d[0]), "+f"(d[1]), "+f"(d[2]), "+f"(d[3])
        : "r"(a[0]), "r"(a[1]), "r"(a[2]), "r"(a[3]), "r"(b[0]), "r"(b[1]));
}

// ---------------- Kernel 0: qW[b,n] = q[b] . Wa_w[n,:] + Wa_b[n] + Ua_b[n] ----------------
__global__ void qw_kernel(const float* __restrict__ query, const float* __restrict__ Wa_w,
                          const float* __restrict__ Wa_b, const float* __restrict__ Ua_b) {
    int b = blockIdx.x;
    int tid = threadIdx.x;                    // 128 threads
    int n = blockIdx.y * 128 + tid;
    __shared__ float4 qs[256];                // q[b] as 1024 floats
    for (int i = tid; i < 256; i += 128) {
        int k = i * 4;
        // q = concat(query[b,1,:], query[b,3,:]); query is (B,4,512)
        const float* src = (k < 512) ? (query + (size_t)b * 2048 + 512 + k)
                                     : (query + (size_t)b * 2048 + 1024 + k);
        qs[i] = *(const float4*)src;
    }
    __syncthreads();
    const float4* wr = (const float4*)(Wa_w + (size_t)n * ND);
    float acc = 0.f;
    #pragma unroll 8
    for (int i = 0; i < 256; i++) {
        float4 a = qs[i], w = wr[i];
        acc += a.x * w.x + a.y * w.y + a.z * w.z + a.w * w.w;
    }
    g_qw[b * ND + n] = acc + Wa_b[n] + Ua_b[n];
}

// ---------------- Kernel 1: tf32 mma.sync GEMM (256x128 CTA, 64x64 warp) ----------------
__global__ void __launch_bounds__(256, 1)
gemm_score_kernel(const float* __restrict__ keys, const float* __restrict__ Ua_w,
                  const float* __restrict__ Va_w) {
    extern __shared__ float sm[];
    float* As = sm + OFF_A;
    float* Bs = sm + OFF_B;
    float* qw_s = sm + OFF_QW;
    float* va_s = sm + OFF_VA;
    float* sc_s = sm + OFF_SC;

    const int tid = threadIdx.x;              // 256 threads, 8 warps
    const int wid = tid >> 5;
    const int lane = tid & 31;
    const int r = lane >> 2;                  // 0..7
    const int c = lane & 3;                   // 0..3
    const int wm = wid & 3;                   // 4 warps along M (64 rows each)
    const int wn = wid >> 2;                  // 2 warps along N (64 cols each)

    const int nt = blockIdx.x;                // N-tile (fast dim -> A reuse in L2)
    const int n0 = nt * T_N;
    const int m0 = blockIdx.y * T_M;
    const int b  = blockIdx.y >> 3;           // 8 M-tiles of 256 per batch (S=2048)

    for (int j = tid; j < T_N; j += 256) {
        qw_s[j] = g_qw[b * ND + n0 + j];
        va_s[j] = Va_w[n0 + j];
    }

    // async tile loader: A = 2048 16B-chunks, B = 1024 chunks; 256 threads
    auto load_tile = [&](int kt, int p) {
        const float* asrc = keys + (size_t)m0 * ND + (size_t)kt * T_K;
        const float* bsrc = Ua_w + (size_t)n0 * ND + (size_t)kt * T_K;
        float* ad = As + p * A_BUF;
        float* bd = Bs + p * B_BUF;
        #pragma unroll
        for (int i = 0; i < 8; i++) {
            int c0 = tid + i * 256;
            int row = c0 >> 3, ch = c0 & 7;
            uint32_t dst = (uint32_t)__cvta_generic_to_shared(ad + row * SA_STRIDE + ch * 4);
            const float* src = asrc + (size_t)row * ND + ch * 4;
            asm volatile("cp.async.cg.shared.global [%0], [%1], 16;" :: "r"(dst), "l"(src));
        }
        #pragma unroll
        for (int i = 0; i < 4; i++) {
            int c0 = tid + i * 256;
            int row = c0 >> 3, ch = c0 & 7;
            uint32_t dst = (uint32_t)__cvta_generic_to_shared(bd + row * SA_STRIDE + ch * 4);
            const float* src = bsrc + (size_t)row * ND + ch * 4;
            asm volatile("cp.async.cg.shared.global [%0], [%1], 16;" :: "r"(dst), "l"(src));
        }
        asm volatile("cp.async.commit_group;");
    };

    float acc[4][8][4];
    #pragma unroll
    for (int im = 0; im < 4; im++)
        #pragma unroll
        for (int in = 0; in < 8; in++)
            #pragma unroll
            for (int k = 0; k < 4; k++) acc[im][in][k] = 0.f;

    load_tile(0, 0);

    for (int kt = 0; kt < NKT; kt++) {
        const int p = kt & 1;
        if (kt + 1 < NKT) {
            load_tile(kt + 1, 1 - p);
            asm volatile("cp.async.wait_group 1;");
        } else {
            asm volatile("cp.async.wait_group 0;");
        }
        __syncthreads();

        const float* ap = As + p * A_BUF;
        const float* bp = Bs + p * B_BUF;
        #pragma unroll
        for (int ks = 0; ks < 4; ks++) {
            const int k0 = ks * 8;
            uint32_t afr[4][4];
            #pragma unroll
            for (int im = 0; im < 4; im++) {
                int row = wm * 64 + im * 16 + r;
                afr[im][0] = f2tf32(ap[row * SA_STRIDE + k0 + c]);
                afr[im][1] = f2tf32(ap[(row + 8) * SA_STRIDE + k0 + c]);
                afr[im][2] = f2tf32(ap[row * SA_STRIDE + k0 + c + 4]);
                afr[im][3] = f2tf32(ap[(row + 8) * SA_STRIDE + k0 + c + 4]);
            }
            #pragma unroll
            for (int in = 0; in < 8; in++) {
                uint32_t bfr[2];
                int n = wn * 64 + in * 8 + r;
                bfr[0] = f2tf32(bp[n * SA_STRIDE + k0 + c]);
                bfr[1] = f2tf32(bp[n * SA_STRIDE + k0 + c + 4]);
                #pragma unroll
                for (int im = 0; im < 4; im++)
                    mma_tf32(acc[im][in], afr[im], bfr);
            }
        }
        __syncthreads();   // before next load overwrites buffer p
    }

    // Epilogue: score_part[m] = sum_n Va[n] * tanh(acc[m][n] + qw[n]) over this CTA's 128 n
    #pragma unroll
    for (int im = 0; im < 4; im++) {
        float rs0 = 0.f, rs1 = 0.f;
        #pragma unroll
        for (int in = 0; in < 8; in++) {
            int col0 = wn * 64 + in * 8 + 2 * c;
            float v0 = va_s[col0],     q0 = qw_s[col0];
            float v1 = va_s[col0 + 1], q1 = qw_s[col0 + 1];
            rs0 += v0 * tanhf(acc[im][in][0] + q0) + v1 * tanhf(acc[im][in][1] + q1);
            rs1 += v0 * tanhf(acc[im][in][2] + q0) + v1 * tanhf(acc[im][in][3] + q1);
        }
        // reduce the 4 lanes sharing each row (lane^1, lane^2 stay in the quad)
        rs0 += __shfl_xor_sync(0xffffffffu, rs0, 1);
        rs0 += __shfl_xor_sync(0xffffffffu, rs0, 2);
        rs1 += __shfl_xor_sync(0xffffffffu, rs1, 1);
        rs1 += __shfl_xor_sync(0xffffffffu, rs1, 2);
        if (c == 0) {
            int rowb = wm * 64 + im * 16 + r;
            sc_s[wn * 256 + rowb] = rs0;
            sc_s[wn * 256 + rowb + 8] = rs1;
        }
    }
    __syncthreads();
    g_scores_part[nt][m0 + tid] = sc_s[tid] + sc_s[256 + tid];
}

// ---------------- Kernel 2: softmax over S per batch, writes weights output ----------------
__global__ void softmax_kernel(float* __restrict__ wts) {
    int b = blockIdx.x;
    int tid = threadIdx.x;                    // 256 threads
    __shared__ float red[8];
    float v[8];
    float mx = -1e30f;
    #pragma unroll
    for (int i = 0; i < 8; i++) {
        int s = tid + i * 256;
        float x = 0.f;
        #pragma unroll
        for (int t = 0; t < NT_N; t++) x += g_scores_part[t][b * NS + s];
        v[i] = x;
        mx = fmaxf(mx, x);
    }
    #pragma unroll
    for (int o = 16; o; o >>= 1) mx = fmaxf(mx, __shfl_xor_sync(0xffffffffu, mx, o));
    if ((tid & 31) == 0) red[tid >> 5] = mx;
    __syncthreads();
    float bm = red[0];
    #pragma unroll
    for (int i = 1; i < 8; i++) bm = fmaxf(bm, red[i]);
    __syncthreads();
    float sum = 0.f;
    #pragma unroll
    for (int i = 0; i < 8; i++) { v[i] = __expf(v[i] - bm); sum += v[i]; }
    #pragma unroll
    for (int o = 16; o; o >>= 1) sum += __shfl_xor_sync(0xffffffffu, sum, o);
    if ((tid & 31) == 0) red[tid >> 5] = sum;
    __syncthreads();
    float bs = 0.f;
    #pragma unroll
    for (int i = 0; i < 8; i++) bs += red[i];
    float inv = 1.0f / bs;
    #pragma unroll
    for (int i = 0; i < 8; i++) wts[b * NS + tid + i * 256] = v[i] * inv;
}

// ---------------- Kernel 3: context partials (s-split for bandwidth) ----------------
__global__ void ctx_part_kernel(const float* __restrict__ keys, const float* __restrict__ wts) {
    int b = blockIdx.x;
    int d = blockIdx.y * 128 + threadIdx.x;
    int z = blockIdx.z;
    int s0 = z * 256;
    __shared__ float ws[256];
    for (int i = threadIdx.x; i < 256; i += 128) ws[i] = wts[b * NS + s0 + i];
    __syncthreads();
    const float* kp = keys + ((size_t)(b * NS + s0)) * ND + d;
    float acc = 0.f;
    #pragma unroll 8
    for (int s = 0; s < 256; s++) acc += ws[s] * kp[(size_t)s * ND];
    g_ctx_part[z][b * ND + d] = acc;
}

// ---------------- Kernel 4: reduce context partials -> output ----------------
__global__ void ctx_reduce_kernel(float* __restrict__ ctx) {
    int b = blockIdx.x;
    int d = threadIdx.x;                      // 1024 threads
    float a = 0.f;
    #pragma unroll
    for (int z = 0; z < 8; z++) a += g_ctx_part[z][b * ND + d];
    ctx[b * ND + d] = a;
}

// ---------------- launch ----------------
extern "C" void kernel_launch(void* const* d_in, const int* in_sizes, int n_in,
                              void* d_out, int out_size) {
    const float* query = (const float*)d_in[0];
    const float* keys  = (const float*)d_in[1];
    const float* Wa_w  = (const float*)d_in[2];
    const float* Wa_b  = (const float*)d_in[3];
    const float* Ua_w  = (const float*)d_in[4];
    const float* Ua_b  = (const float*)d_in[5];
    const float* Va_w  = (const float*)d_in[6];
    // Va_b (d_in[7]) cancels in softmax; scores are not an output.

    float* out = (float*)d_out;
    float* ctx = out;                                  // (B,1,2H) = 32768 floats
    float* wts = (out_size >= NB * ND + NB * NS) ? out + NB * ND : out;  // (B,1,S)

    cudaFuncSetAttribute(gemm_score_kernel, cudaFuncAttributeMaxDynamicSharedMemorySize, SMEM_BYTES);

    qw_kernel<<<dim3(NB, 8), 128>>>(query, Wa_w, Wa_b, Ua_b);
    gemm_score_kernel<<<dim3(NT_N, BSR / T_M), 256, SMEM_BYTES>>>(keys, Ua_w, Va_w);
    softmax_kernel<<<NB, 256>>>(wts);
    ctx_part_kernel<<<dim3(NB, 8, 8), 128>>>(keys, wts);
    ctx_reduce_kernel<<<NB, 1024>>>(ctx);
}

// round 5
// speedup vs baseline: 1.5029x; 1.5019x over previous
#include <cuda_runtime.h>
#include <cuda_fp16.h>
#include <cstdint>
#include <math.h>

// Problem constants
#define NB   32
#define NS   2048
#define ND   1024
#define BSR  65536      // NB*NS rows
#define T_M  256
#define T_N  128
#define T_K  32
#define NKT  32         // ND / T_K
#define NT_N 8          // 1024 / 128 N-tiles

// Device scratch (no dynamic allocation allowed)
__device__ float g_qw[NB * ND];
__device__ float g_scores_part[NT_N][BSR];
__device__ float g_ctx_part[8][NB * ND];
__device__ uint4 g_keys_h4[(size_t)BSR * ND / 8];   // keys as fp16, 128 MB
__device__ uint4 g_ua_h4[ND * ND / 8];              // Ua_w as fp16, 2 MB

// ---------------- smem layout for gemm kernel ----------------
#define SA_S   40                          // halves per row (80B, conflict-free & 16B-mult)
#define A_BUFH (T_M * SA_S)                // 10240 halves
#define B_BUFH (T_N * SA_S)                // 5120 halves
#define OFF_A  0                           // bytes
#define OFF_B  (2 * A_BUFH * 2)            // 40960
#define OFF_QW (OFF_B + 2 * B_BUFH * 2)    // 61440
#define OFF_VA (OFF_QW + 512)
#define OFF_SC (OFF_VA + 512)
#define SMEM_BYTES (OFF_SC + 2048)         // 64512

__device__ __forceinline__ void mma_f16(float* d, const uint32_t* a, const uint32_t* b) {
    asm volatile(
        "mma.sync.aligned.m16n8k16.row.col.f32.f16.f16.f32 "
        "{%0,%1,%2,%3}, {%4,%5,%6,%7}, {%8,%9}, {%0,%1,%2,%3};"
        : "+f"(d[0]), "+f"(d[1]), "+f"(d[2]), "+f"(d[3])
        : "r"(a[0]), "r"(a[1]), "r"(a[2]), "r"(a[3]), "r"(b[0]), "r"(b[1]));
}

__device__ __forceinline__ uint32_t pack2h(float x, float y) {
    __half2 h = __floats2half2_rn(x, y);
    return *(uint32_t*)&h;
}

// ---------------- Kernel A: fp32 -> fp16 converters ----------------
__global__ void cvt_kernel(const float4* __restrict__ src, uint4* __restrict__ dst) {
    size_t i = (size_t)blockIdx.x * blockDim.x + threadIdx.x;   // one uint4 = 8 halves
    float4 a = src[2 * i];
    float4 b = src[2 * i + 1];
    uint4 u;
    u.x = pack2h(a.x, a.y);
    u.y = pack2h(a.z, a.w);
    u.z = pack2h(b.x, b.y);
    u.w = pack2h(b.z, b.w);
    dst[i] = u;
}

// ---------------- Kernel 0: qW[b,n] = q[b] . Wa_w[n,:] + Wa_b[n] + Ua_b[n] ----------------
__global__ void qw_kernel(const float* __restrict__ query, const float* __restrict__ Wa_w,
                          const float* __restrict__ Wa_b, const float* __restrict__ Ua_b) {
    int b = blockIdx.x;
    int tid = threadIdx.x;                    // 128 threads
    int n = blockIdx.y * 128 + tid;
    __shared__ float4 qs[256];                // q[b] as 1024 floats
    for (int i = tid; i < 256; i += 128) {
        int k = i * 4;
        // q = concat(query[b,1,:], query[b,3,:]); query is (B,4,512)
        const float* src = (k < 512) ? (query + (size_t)b * 2048 + 512 + k)
                                     : (query + (size_t)b * 2048 + 1024 + k);
        qs[i] = *(const float4*)src;
    }
    __syncthreads();
    const float4* wr = (const float4*)(Wa_w + (size_t)n * ND);
    float acc = 0.f;
    #pragma unroll 8
    for (int i = 0; i < 256; i++) {
        float4 a = qs[i], w = wr[i];
        acc += a.x * w.x + a.y * w.y + a.z * w.z + a.w * w.w;
    }
    g_qw[b * ND + n] = acc + Wa_b[n] + Ua_b[n];
}

// ---------------- Kernel 1: fp16 mma.sync GEMM (256x128 CTA, 64x64 warp) ----------------
__global__ void __launch_bounds__(256, 1)
gemm_score_kernel(const float* __restrict__ Va_w) {
    extern __shared__ __align__(16) char smc[];
    __half* As = (__half*)(smc + OFF_A);
    __half* Bs = (__half*)(smc + OFF_B);
    float* qw_s = (float*)(smc + OFF_QW);
    float* va_s = (float*)(smc + OFF_VA);
    float* sc_s = (float*)(smc + OFF_SC);

    const __half* keys_h = (const __half*)g_keys_h4;
    const __half* ua_h   = (const __half*)g_ua_h4;

    const int tid = threadIdx.x;              // 256 threads, 8 warps
    const int wid = tid >> 5;
    const int lane = tid & 31;
    const int r = lane >> 2;                  // 0..7
    const int c = lane & 3;                   // 0..3
    const int wm = wid & 3;                   // 4 warps along M (64 rows each)
    const int wn = wid >> 2;                  // 2 warps along N (64 cols each)

    const int nt = blockIdx.x;                // N-tile (fast dim -> A reuse in L2)
    const int n0 = nt * T_N;
    const int m0 = blockIdx.y * T_M;
    const int b  = blockIdx.y >> 3;           // 8 M-tiles of 256 per batch (S=2048)

    for (int j = tid; j < T_N; j += 256) {
        qw_s[j] = g_qw[b * ND + n0 + j];
        va_s[j] = Va_w[n0 + j];
    }

    // async tile loader (fp16): A = 1024 16B-chunks (4/row), B = 512 chunks
    auto load_tile = [&](int kt, int p) {
        const __half* asrc = keys_h + (size_t)m0 * ND + (size_t)kt * T_K;
        const __half* bsrc = ua_h + (size_t)n0 * ND + (size_t)kt * T_K;
        __half* ad = As + p * A_BUFH;
        __half* bd = Bs + p * B_BUFH;
        #pragma unroll
        for (int i = 0; i < 4; i++) {
            int c0 = tid + i * 256;
            int row = c0 >> 2, ch = c0 & 3;
            uint32_t dst = (uint32_t)__cvta_generic_to_shared(ad + row * SA_S + ch * 8);
            const __half* src = asrc + (size_t)row * ND + ch * 8;
            asm volatile("cp.async.cg.shared.global [%0], [%1], 16;" :: "r"(dst), "l"(src));
        }
        #pragma unroll
        for (int i = 0; i < 2; i++) {
            int c0 = tid + i * 256;
            int row = c0 >> 2, ch = c0 & 3;
            uint32_t dst = (uint32_t)__cvta_generic_to_shared(bd + row * SA_S + ch * 8);
            const __half* src = bsrc + (size_t)row * ND + ch * 8;
            asm volatile("cp.async.cg.shared.global [%0], [%1], 16;" :: "r"(dst), "l"(src));
        }
        asm volatile("cp.async.commit_group;");
    };

    float acc[4][8][4];
    #pragma unroll
    for (int im = 0; im < 4; im++)
        #pragma unroll
        for (int in = 0; in < 8; in++)
            #pragma unroll
            for (int k = 0; k < 4; k++) acc[im][in][k] = 0.f;

    load_tile(0, 0);

    for (int kt = 0; kt < NKT; kt++) {
        const int p = kt & 1;
        if (kt + 1 < NKT) {
            load_tile(kt + 1, 1 - p);
            asm volatile("cp.async.wait_group 1;");
        } else {
            asm volatile("cp.async.wait_group 0;");
        }
        __syncthreads();

        const __half* ap = As + p * A_BUFH;
        const __half* bp = Bs + p * B_BUFH;
        #pragma unroll
        for (int ks = 0; ks < 2; ks++) {          // two k16 steps per 32-K tile
            const int k0 = ks * 16;
            uint32_t afr[4][4];
            #pragma unroll
            for (int im = 0; im < 4; im++) {
                int row = wm * 64 + im * 16 + r;
                const __half* p0 = ap + row * SA_S + k0 + 2 * c;
                const __half* p1 = ap + (row + 8) * SA_S + k0 + 2 * c;
                afr[im][0] = *(const uint32_t*)p0;        // (r,   k0+2c..+1)
                afr[im][1] = *(const uint32_t*)p1;        // (r+8, k0+2c..+1)
                afr[im][2] = *(const uint32_t*)(p0 + 8);  // (r,   k0+2c+8..+9)
                afr[im][3] = *(const uint32_t*)(p1 + 8);  // (r+8, ...)
            }
            #pragma unroll
            for (int in = 0; in < 8; in++) {
                int n = wn * 64 + in * 8 + r;
                const __half* pb = bp + n * SA_S + k0 + 2 * c;
                uint32_t bfr[2];
                bfr[0] = *(const uint32_t*)pb;            // (k0+2c..+1,   n)
                bfr[1] = *(const uint32_t*)(pb + 8);      // (k0+2c+8..+9, n)
                #pragma unroll
                for (int im = 0; im < 4; im++)
                    mma_f16(acc[im][in], afr[im], bfr);
            }
        }
        __syncthreads();   // before next load overwrites buffer p
    }

    // Epilogue: score_part[m] = sum_n Va[n] * tanh(acc[m][n] + qw[n]) over this CTA's 128 n
    #pragma unroll
    for (int im = 0; im < 4; im++) {
        float rs0 = 0.f, rs1 = 0.f;
        #pragma unroll
        for (int in = 0; in < 8; in++) {
            int col0 = wn * 64 + in * 8 + 2 * c;
            float v0 = va_s[col0],     q0 = qw_s[col0];
            float v1 = va_s[col0 + 1], q1 = qw_s[col0 + 1];
            rs0 += v0 * tanhf(acc[im][in][0] + q0) + v1 * tanhf(acc[im][in][1] + q1);
            rs1 += v0 * tanhf(acc[im][in][2] + q0) + v1 * tanhf(acc[im][in][3] + q1);
        }
        // reduce the 4 lanes sharing each row (lane^1, lane^2 stay in the quad)
        rs0 += __shfl_xor_sync(0xffffffffu, rs0, 1);
        rs0 += __shfl_xor_sync(0xffffffffu, rs0, 2);
        rs1 += __shfl_xor_sync(0xffffffffu, rs1, 1);
        rs1 += __shfl_xor_sync(0xffffffffu, rs1, 2);
        if (c == 0) {
            int rowb = wm * 64 + im * 16 + r;
            sc_s[wn * 256 + rowb] = rs0;
            sc_s[wn * 256 + rowb + 8] = rs1;
        }
    }
    __syncthreads();
    g_scores_part[nt][m0 + tid] = sc_s[tid] + sc_s[256 + tid];
}

// ---------------- Kernel 2: softmax over S per batch, writes weights output ----------------
__global__ void softmax_kernel(float* __restrict__ wts) {
    int b = blockIdx.x;
    int tid = threadIdx.x;                    // 256 threads
    __shared__ float red[8];
    float v[8];
    float mx = -1e30f;
    #pragma unroll
    for (int i = 0; i < 8; i++) {
        int s = tid + i * 256;
        float x = 0.f;
        #pragma unroll
        for (int t = 0; t < NT_N; t++) x += g_scores_part[t][b * NS + s];
        v[i] = x;
        mx = fmaxf(mx, x);
    }
    #pragma unroll
    for (int o = 16; o; o >>= 1) mx = fmaxf(mx, __shfl_xor_sync(0xffffffffu, mx, o));
    if ((tid & 31) == 0) red[tid >> 5] = mx;
    __syncthreads();
    float bm = red[0];
    #pragma unroll
    for (int i = 1; i < 8; i++) bm = fmaxf(bm, red[i]);
    __syncthreads();
    float sum = 0.f;
    #pragma unroll
    for (int i = 0; i < 8; i++) { v[i] = __expf(v[i] - bm); sum += v[i]; }
    #pragma unroll
    for (int o = 16; o; o >>= 1) sum += __shfl_xor_sync(0xffffffffu, sum, o);
    if ((tid & 31) == 0) red[tid >> 5] = sum;
    __syncthreads();
    float bs = 0.f;
    #pragma unroll
    for (int i = 0; i < 8; i++) bs += red[i];
    float inv = 1.0f / bs;
    #pragma unroll
    for (int i = 0; i < 8; i++) wts[b * NS + tid + i * 256] = v[i] * inv;
}

// ---------------- Kernel 3: context partials (s-split for bandwidth) ----------------
__global__ void ctx_part_kernel(const float* __restrict__ keys, const float* __restrict__ wts) {
    int b = blockIdx.x;
    int d = blockIdx.y * 128 + threadIdx.x;
    int z = blockIdx.z;
    int s0 = z * 256;
    __shared__ float ws[256];
    for (int i = threadIdx.x; i < 256; i += 128) ws[i] = wts[b * NS + s0 + i];
    __syncthreads();
    const float* kp = keys + ((size_t)(b * NS + s0)) * ND + d;
    float acc = 0.f;
    #pragma unroll 8
    for (int s = 0; s < 256; s++) acc += ws[s] * kp[(size_t)s * ND];
    g_ctx_part[z][b * ND + d] = acc;
}

// ---------------- Kernel 4: reduce context partials -> output ----------------
__global__ void ctx_reduce_kernel(float* __restrict__ ctx) {
    int b = blockIdx.x;
    int d = threadIdx.x;                      // 1024 threads
    float a = 0.f;
    #pragma unroll
    for (int z = 0; z < 8; z++) a += g_ctx_part[z][b * ND + d];
    ctx[b * ND + d] = a;
}

// ---------------- launch ----------------
extern "C" void kernel_launch(void* const* d_in, const int* in_sizes, int n_in,
                              void* d_out, int out_size) {
    const float* query = (const float*)d_in[0];
    const float* keys  = (const float*)d_in[1];
    const float* Wa_w  = (const float*)d_in[2];
    const float* Wa_b  = (const float*)d_in[3];
    const float* Ua_w  = (const float*)d_in[4];
    const float* Ua_b  = (const float*)d_in[5];
    const float* Va_w  = (const float*)d_in[6];
    // Va_b (d_in[7]) cancels in softmax; scores are not an output.

    float* out = (float*)d_out;
    float* ctx = out;                                  // (B,1,2H) = 32768 floats
    float* wts = (out_size >= NB * ND + NB * NS) ? out + NB * ND : out;  // (B,1,S)

    uint4* keys_h4;  cudaGetSymbolAddress((void**)&keys_h4, g_keys_h4);
    uint4* ua_h4;    cudaGetSymbolAddress((void**)&ua_h4, g_ua_h4);

    cudaFuncSetAttribute(gemm_score_kernel, cudaFuncAttributeMaxDynamicSharedMemorySize, SMEM_BYTES);

    cvt_kernel<<<(size_t)BSR * ND / 8 / 256, 256>>>((const float4*)keys, keys_h4);
    cvt_kernel<<<ND * ND / 8 / 256, 256>>>((const float4*)Ua_w, ua_h4);
    qw_kernel<<<dim3(NB, 8), 128>>>(query, Wa_w, Wa_b, Ua_b);
    gemm_score_kernel<<<dim3(NT_N, BSR / T_M), 256, SMEM_BYTES>>>(Va_w);
    softmax_kernel<<<NB, 256>>>(wts);
    ctx_part_kernel<<<dim3(NB, 8, 8), 128>>>(keys, wts);
    ctx_reduce_kernel<<<NB, 1024>>>(ctx);
}

// round 6
// speedup vs baseline: 1.7670x; 1.1757x over previous
#include <cuda_runtime.h>
#include <cuda_fp16.h>
#include <cstdint>
#include <math.h>

// Problem constants
#define NB   32
#define NS   2048
#define ND   1024
#define BSR  65536      // NB*NS rows
#define T_M  128
#define T_N  128
#define T_K  32
#define NKT  32         // ND / T_K
#define NT_N 8          // 1024 / 128 N-tiles

// Device scratch (no dynamic allocation allowed)
__device__ float g_qw[NB * ND];
__device__ float g_scores_part[NT_N][BSR];
__device__ float g_ctx_part[8][NB * ND];
__device__ uint4 g_keys_h4[(size_t)BSR * ND / 8];   // keys as fp16, 128 MB
__device__ uint4 g_ua_h4[ND * ND / 8];              // Ua_w as fp16, 2 MB

// ---------------- smem layout for gemm kernel (bytes) ----------------
#define SA_S     40                        // halves per row (80B: ldmatrix conflict-free)
#define STAGE_B  (T_M * SA_S * 2)          // 10240 bytes per stage per matrix
#define OFF_A    0                         // 3 stages: 30720
#define OFF_B    30720                     // 3 stages: 30720
#define OFF_QW   61440                     // 128 floats
#define OFF_VA   61952                     // 128 floats
#define OFF_SC   62464                     // 256 floats
#define SMEM_BYTES 63488

__device__ __forceinline__ void mma_f16(float* d, const uint32_t* a, const uint32_t* b) {
    asm volatile(
        "mma.sync.aligned.m16n8k16.row.col.f32.f16.f16.f32 "
        "{%0,%1,%2,%3}, {%4,%5,%6,%7}, {%8,%9}, {%0,%1,%2,%3};"
        : "+f"(d[0]), "+f"(d[1]), "+f"(d[2]), "+f"(d[3])
        : "r"(a[0]), "r"(a[1]), "r"(a[2]), "r"(a[3]), "r"(b[0]), "r"(b[1]));
}

__device__ __forceinline__ void ldsm_x4(uint32_t* r, uint32_t addr) {
    asm volatile("ldmatrix.sync.aligned.m8n8.x4.shared.b16 {%0,%1,%2,%3}, [%4];"
        : "=r"(r[0]), "=r"(r[1]), "=r"(r[2]), "=r"(r[3]) : "r"(addr));
}

__device__ __forceinline__ uint32_t pack2h(float x, float y) {
    __half2 h = __floats2half2_rn(x, y);
    return *(uint32_t*)&h;
}

// ---------------- Kernel A: fp32 -> fp16 converters ----------------
__global__ void cvt_kernel(const float4* __restrict__ src, uint4* __restrict__ dst) {
    size_t i = (size_t)blockIdx.x * blockDim.x + threadIdx.x;   // one uint4 = 8 halves
    float4 a = src[2 * i];
    float4 b = src[2 * i + 1];
    uint4 u;
    u.x = pack2h(a.x, a.y);
    u.y = pack2h(a.z, a.w);
    u.z = pack2h(b.x, b.y);
    u.w = pack2h(b.z, b.w);
    dst[i] = u;
}

// ---------------- Kernel 0: qW[b,n] = q[b] . Wa_w[n,:] + Wa_b[n] + Ua_b[n] ----------------
__global__ void qw_kernel(const float* __restrict__ query, const float* __restrict__ Wa_w,
                          const float* __restrict__ Wa_b, const float* __restrict__ Ua_b) {
    int b = blockIdx.x;
    int tid = threadIdx.x;                    // 128 threads
    int n = blockIdx.y * 128 + tid;
    __shared__ float4 qs[256];                // q[b] as 1024 floats
    for (int i = tid; i < 256; i += 128) {
        int k = i * 4;
        // q = concat(query[b,1,:], query[b,3,:]); query is (B,4,512)
        const float* src = (k < 512) ? (query + (size_t)b * 2048 + 512 + k)
                                     : (query + (size_t)b * 2048 + 1024 + k);
        qs[i] = *(const float4*)src;
    }
    __syncthreads();
    const float4* wr = (const float4*)(Wa_w + (size_t)n * ND);
    float acc = 0.f;
    #pragma unroll 8
    for (int i = 0; i < 256; i++) {
        float4 a = qs[i], w = wr[i];
        acc += a.x * w.x + a.y * w.y + a.z * w.z + a.w * w.w;
    }
    g_qw[b * ND + n] = acc + Wa_b[n] + Ua_b[n];
}

// ---------------- Kernel 1: fp16 mma GEMM (128x128 CTA, 32x64 warp, 2 CTA/SM) ----------------
__global__ void __launch_bounds__(256, 2)
gemm_score_kernel(const float* __restrict__ Va_w) {
    extern __shared__ __align__(16) char smc[];
    float* qw_s = (float*)(smc + OFF_QW);
    float* va_s = (float*)(smc + OFF_VA);
    float* sc_s = (float*)(smc + OFF_SC);

    const __half* keys_h = (const __half*)g_keys_h4;
    const __half* ua_h   = (const __half*)g_ua_h4;

    const int tid = threadIdx.x;              // 256 threads, 8 warps
    const int wid = tid >> 5;
    const int lane = tid & 31;
    const int r = lane >> 2;                  // 0..7
    const int c = lane & 3;                   // 0..3
    const int wm = wid & 3;                   // 4 warps along M (32 rows each)
    const int wn = wid >> 2;                  // 2 warps along N (64 cols each)

    const int nt = blockIdx.x;                // N-tile (fast dim -> A reuse in L2)
    const int n0 = nt * T_N;
    const int m0 = blockIdx.y * T_M;
    const int b  = blockIdx.y >> 4;           // 16 M-tiles of 128 per batch

    const uint32_t sbase = (uint32_t)__cvta_generic_to_shared(smc);
    const uint32_t sA = sbase + OFF_A;
    const uint32_t sB = sbase + OFF_B;

    // ldmatrix per-lane offsets (bytes)
    const uint32_t a_lane_off = (uint32_t)(((lane & 15) * SA_S + ((lane >> 4) << 3)) * 2);
    const uint32_t b_lane_off = (uint32_t)(((((lane >> 4) << 3) + (lane & 7)) * SA_S
                                            + (((lane >> 3) & 1) << 3)) * 2);

    // async tile loader: 512 16B-chunks per matrix, 256 threads => 2 each
    auto load_tile = [&](int kt, int p) {
        const __half* asrc = keys_h + (size_t)m0 * ND + (size_t)kt * T_K;
        const __half* bsrc = ua_h + (size_t)n0 * ND + (size_t)kt * T_K;
        uint32_t ad = sA + p * STAGE_B;
        uint32_t bd = sB + p * STAGE_B;
        #pragma unroll
        for (int i = 0; i < 2; i++) {
            int c0 = tid + i * 256;
            int row = c0 >> 2, ch = c0 & 3;
            uint32_t off = (uint32_t)((row * SA_S + ch * 8) * 2);
            asm volatile("cp.async.cg.shared.global [%0], [%1], 16;"
                :: "r"(ad + off), "l"(asrc + (size_t)row * ND + ch * 8));
            asm volatile("cp.async.cg.shared.global [%0], [%1], 16;"
                :: "r"(bd + off), "l"(bsrc + (size_t)row * ND + ch * 8));
        }
        asm volatile("cp.async.commit_group;");
    };

    load_tile(0, 0);
    load_tile(1, 1);

    for (int j = tid; j < T_N; j += 256) {
        qw_s[j] = g_qw[b * ND + n0 + j];
        va_s[j] = Va_w[n0 + j];
    }

    float acc[2][8][4];
    #pragma unroll
    for (int im = 0; im < 2; im++)
        #pragma unroll
        for (int in = 0; in < 8; in++)
            #pragma unroll
            for (int k = 0; k < 4; k++) acc[im][in][k] = 0.f;

    int p = 0;
    for (int kt = 0; kt < NKT; kt++) {
        if (kt < NKT - 1) { asm volatile("cp.async.wait_group 1;"); }
        else             { asm volatile("cp.async.wait_group 0;"); }
        __syncthreads();      // prev-iter compute done + tile kt visible to all
        if (kt + 2 < NKT) {
            int pn = p + 2; if (pn >= 3) pn -= 3;
            load_tile(kt + 2, pn);
        }

        const uint32_t ap = sA + p * STAGE_B + wm * (32 * SA_S * 2) + a_lane_off;
        const uint32_t bp = sB + p * STAGE_B + wn * (64 * SA_S * 2) + b_lane_off;
        #pragma unroll
        for (int ks = 0; ks < 2; ks++) {
            const uint32_t ko = ks * 32;      // 16 halves
            uint32_t afr[2][4], bfr[4][4];
            ldsm_x4(afr[0], ap + ko);
            ldsm_x4(afr[1], ap + 16 * SA_S * 2 + ko);
            #pragma unroll
            for (int ip = 0; ip < 4; ip++)
                ldsm_x4(bfr[ip], bp + ip * (16 * SA_S * 2) + ko);
            #pragma unroll
            for (int in = 0; in < 8; in++) {
                const uint32_t* bb = &bfr[in >> 1][(in & 1) * 2];
                mma_f16(acc[0][in], afr[0], bb);
                mma_f16(acc[1][in], afr[1], bb);
            }
        }
        p++; if (p == 3) p = 0;
    }

    // Epilogue: score_part[m] = sum_n Va[n] * tanh(acc[m][n] + qw[n]) over this CTA's 128 n
    #pragma unroll
    for (int im = 0; im < 2; im++) {
        float rs0 = 0.f, rs1 = 0.f;
        #pragma unroll
        for (int in = 0; in < 8; in++) {
            int col0 = wn * 64 + in * 8 + 2 * c;
            float v0 = va_s[col0],     q0 = qw_s[col0];
            float v1 = va_s[col0 + 1], q1 = qw_s[col0 + 1];
            rs0 += v0 * tanhf(acc[im][in][0] + q0) + v1 * tanhf(acc[im][in][1] + q1);
            rs1 += v0 * tanhf(acc[im][in][2] + q0) + v1 * tanhf(acc[im][in][3] + q1);
        }
        // reduce the 4 lanes sharing each row (lane^1, lane^2 stay in the quad)
        rs0 += __shfl_xor_sync(0xffffffffu, rs0, 1);
        rs0 += __shfl_xor_sync(0xffffffffu, rs0, 2);
        rs1 += __shfl_xor_sync(0xffffffffu, rs1, 1);
        rs1 += __shfl_xor_sync(0xffffffffu, rs1, 2);
        if (c == 0) {
            int rowb = wm * 32 + im * 16 + r;
            sc_s[wn * 128 + rowb] = rs0;
            sc_s[wn * 128 + rowb + 8] = rs1;
        }
    }
    __syncthreads();
    if (tid < 128)
        g_scores_part[nt][m0 + tid] = sc_s[tid] + sc_s[128 + tid];
}

// ---------------- Kernel 2: softmax over S per batch, writes weights output ----------------
__global__ void softmax_kernel(float* __restrict__ wts) {
    int b = blockIdx.x;
    int tid = threadIdx.x;                    // 256 threads
    __shared__ float red[8];
    float v[8];
    float mx = -1e30f;
    #pragma unroll
    for (int i = 0; i < 8; i++) {
        int s = tid + i * 256;
        float x = 0.f;
        #pragma unroll
        for (int t = 0; t < NT_N; t++) x += g_scores_part[t][b * NS + s];
        v[i] = x;
        mx = fmaxf(mx, x);
    }
    #pragma unroll
    for (int o = 16; o; o >>= 1) mx = fmaxf(mx, __shfl_xor_sync(0xffffffffu, mx, o));
    if ((tid & 31) == 0) red[tid >> 5] = mx;
    __syncthreads();
    float bm = red[0];
    #pragma unroll
    for (int i = 1; i < 8; i++) bm = fmaxf(bm, red[i]);
    __syncthreads();
    float sum = 0.f;
    #pragma unroll
    for (int i = 0; i < 8; i++) { v[i] = __expf(v[i] - bm); sum += v[i]; }
    #pragma unroll
    for (int o = 16; o; o >>= 1) sum += __shfl_xor_sync(0xffffffffu, sum, o);
    if ((tid & 31) == 0) red[tid >> 5] = sum;
    __syncthreads();
    float bs = 0.f;
    #pragma unroll
    for (int i = 0; i < 8; i++) bs += red[i];
    float inv = 1.0f / bs;
    #pragma unroll
    for (int i = 0; i < 8; i++) wts[b * NS + tid + i * 256] = v[i] * inv;
}

// ---------------- Kernel 3: context partials (s-split for bandwidth) ----------------
__global__ void ctx_part_kernel(const float* __restrict__ keys, const float* __restrict__ wts) {
    int b = blockIdx.x;
    int d = blockIdx.y * 128 + threadIdx.x;
    int z = blockIdx.z;
    int s0 = z * 256;
    __shared__ float ws[256];
    for (int i = threadIdx.x; i < 256; i += 128) ws[i] = wts[b * NS + s0 + i];
    __syncthreads();
    const float* kp = keys + ((size_t)(b * NS + s0)) * ND + d;
    float acc = 0.f;
    #pragma unroll 8
    for (int s = 0; s < 256; s++) acc += ws[s] * kp[(size_t)s * ND];
    g_ctx_part[z][b * ND + d] = acc;
}

// ---------------- Kernel 4: reduce context partials -> output ----------------
__global__ void ctx_reduce_kernel(float* __restrict__ ctx) {
    int b = blockIdx.x;
    int d = threadIdx.x;                      // 1024 threads
    float a = 0.f;
    #pragma unroll
    for (int z = 0; z < 8; z++) a += g_ctx_part[z][b * ND + d];
    ctx[b * ND + d] = a;
}

// ---------------- launch ----------------
extern "C" void kernel_launch(void* const* d_in, const int* in_sizes, int n_in,
                              void* d_out, int out_size) {
    const float* query = (const float*)d_in[0];
    const float* keys  = (const float*)d_in[1];
    const float* Wa_w  = (const float*)d_in[2];
    const float* Wa_b  = (const float*)d_in[3];
    const float* Ua_w  = (const float*)d_in[4];
    const float* Ua_b  = (const float*)d_in[5];
    const float* Va_w  = (const float*)d_in[6];
    // Va_b (d_in[7]) cancels in softmax; scores are not an output.

    float* out = (float*)d_out;
    float* ctx = out;                                  // (B,1,2H) = 32768 floats
    float* wts = (out_size >= NB * ND + NB * NS) ? out + NB * ND : out;  // (B,1,S)

    uint4* keys_h4;  cudaGetSymbolAddress((void**)&keys_h4, g_keys_h4);
    uint4* ua_h4;    cudaGetSymbolAddress((void**)&ua_h4, g_ua_h4);

    cudaFuncSetAttribute(gemm_score_kernel, cudaFuncAttributeMaxDynamicSharedMemorySize, SMEM_BYTES);

    cvt_kernel<<<(size_t)BSR * ND / 8 / 256, 256>>>((const float4*)keys, keys_h4);
    cvt_kernel<<<ND * ND / 8 / 256, 256>>>((const float4*)Ua_w, ua_h4);
    qw_kernel<<<dim3(NB, 8), 128>>>(query, Wa_w, Wa_b, Ua_b);
    gemm_score_kernel<<<dim3(NT_N, BSR / T_M), 256, SMEM_BYTES>>>(Va_w);
    softmax_kernel<<<NB, 256>>>(wts);
    ctx_part_kernel<<<dim3(NB, 8, 8), 128>>>(keys, wts);
    ctx_reduce_kernel<<<NB, 1024>>>(ctx);
}

// round 7
// speedup vs baseline: 1.9051x; 1.0782x over previous
#include <cuda_runtime.h>
#include <cuda_fp16.h>
#include <cstdint>
#include <math.h>

// Problem constants
#define NB   32
#define NS   2048
#define ND   1024
#define BSR  65536      // NB*NS rows
#define T_M  128
#define T_N  128
#define T_K  32
#define NKT  32         // ND / T_K
#define NT_N 8          // 1024 / 128 N-tiles

// Device scratch (no dynamic allocation allowed)
__device__ float g_qw[NB * ND];
__device__ float g_scores_part[NT_N][BSR];
__device__ float g_ctx_part[8][NB * ND];
__device__ uint4 g_keys_h4[(size_t)BSR * ND / 8];   // keys as fp16, 128 MB
__device__ uint4 g_ua_h4[ND * ND / 8];              // Ua_w as fp16, 2 MB

// ---------------- smem layout for gemm kernel (bytes) ----------------
#define SA_S     40                        // halves per row (80B: ldmatrix conflict-free)
#define STAGE_B  (T_M * SA_S * 2)          // 10240 bytes per stage per matrix
#define NSTAGE   4
#define OFF_A    0                         // 4 stages: 40960
#define OFF_B    40960                     // 4 stages: 40960
#define OFF_QW   81920                     // 128 floats
#define OFF_VA   82432                     // 128 floats
#define OFF_SC   82944                     // 256 floats
#define SMEM_BYTES 83968

__device__ __forceinline__ void mma_f16(float* d, const uint32_t* a, const uint32_t* b) {
    asm volatile(
        "mma.sync.aligned.m16n8k16.row.col.f32.f16.f16.f32 "
        "{%0,%1,%2,%3}, {%4,%5,%6,%7}, {%8,%9}, {%0,%1,%2,%3};"
        : "+f"(d[0]), "+f"(d[1]), "+f"(d[2]), "+f"(d[3])
        : "r"(a[0]), "r"(a[1]), "r"(a[2]), "r"(a[3]), "r"(b[0]), "r"(b[1]));
}

__device__ __forceinline__ void ldsm_x4(uint32_t* r, uint32_t addr) {
    asm volatile("ldmatrix.sync.aligned.m8n8.x4.shared.b16 {%0,%1,%2,%3}, [%4];"
        : "=r"(r[0]), "=r"(r[1]), "=r"(r[2]), "=r"(r[3]) : "r"(addr));
}

__device__ __forceinline__ uint32_t pack2h(float x, float y) {
    __half2 h = __floats2half2_rn(x, y);
    return *(uint32_t*)&h;
}

// ---------------- Kernel A: fp32 -> fp16 converters ----------------
__global__ void cvt_kernel(const float4* __restrict__ src, uint4* __restrict__ dst) {
    size_t i = (size_t)blockIdx.x * blockDim.x + threadIdx.x;   // one uint4 = 8 halves
    float4 a = src[2 * i];
    float4 b = src[2 * i + 1];
    uint4 u;
    u.x = pack2h(a.x, a.y);
    u.y = pack2h(a.z, a.w);
    u.z = pack2h(b.x, b.y);
    u.w = pack2h(b.z, b.w);
    dst[i] = u;
}

// ---------------- Kernel 0: qW[b,n] = q[b] . Wa_w[n,:] + Wa_b[n] + Ua_b[n] ----------------
__global__ void qw_kernel(const float* __restrict__ query, const float* __restrict__ Wa_w,
                          const float* __restrict__ Wa_b, const float* __restrict__ Ua_b) {
    int b = blockIdx.x;
    int tid = threadIdx.x;                    // 128 threads
    int n = blockIdx.y * 128 + tid;
    __shared__ float4 qs[256];                // q[b] as 1024 floats
    for (int i = tid; i < 256; i += 128) {
        int k = i * 4;
        // q = concat(query[b,1,:], query[b,3,:]); query is (B,4,512)
        const float* src = (k < 512) ? (query + (size_t)b * 2048 + 512 + k)
                                     : (query + (size_t)b * 2048 + 1024 + k);
        qs[i] = *(const float4*)src;
    }
    __syncthreads();
    const float4* wr = (const float4*)(Wa_w + (size_t)n * ND);
    float acc = 0.f;
    #pragma unroll 8
    for (int i = 0; i < 256; i++) {
        float4 a = qs[i], w = wr[i];
        acc += a.x * w.x + a.y * w.y + a.z * w.z + a.w * w.w;
    }
    g_qw[b * ND + n] = acc + Wa_b[n] + Ua_b[n];
}

// ---------------- Kernel 1: fp16 mma GEMM (128x128 CTA, 4 warps of 64x64, 2 CTA/SM) ----------------
__global__ void __launch_bounds__(128, 2)
gemm_score_kernel(const float* __restrict__ Va_w) {
    extern __shared__ __align__(16) char smc[];
    float* qw_s = (float*)(smc + OFF_QW);
    float* va_s = (float*)(smc + OFF_VA);
    float* sc_s = (float*)(smc + OFF_SC);

    const __half* keys_h = (const __half*)g_keys_h4;
    const __half* ua_h   = (const __half*)g_ua_h4;

    const int tid = threadIdx.x;              // 128 threads, 4 warps
    const int wid = tid >> 5;
    const int lane = tid & 31;
    const int r = lane >> 2;                  // 0..7
    const int c = lane & 3;                   // 0..3
    const int wm = wid & 1;                   // 2 warps along M (64 rows each)
    const int wn = wid >> 1;                  // 2 warps along N (64 cols each)

    const int nt = blockIdx.x;                // N-tile (fast dim -> A reuse in L2)
    const int n0 = nt * T_N;
    const int m0 = blockIdx.y * T_M;
    const int b  = blockIdx.y >> 4;           // 16 M-tiles of 128 per batch

    const uint32_t sbase = (uint32_t)__cvta_generic_to_shared(smc);
    const uint32_t sA = sbase + OFF_A;
    const uint32_t sB = sbase + OFF_B;

    // ldmatrix per-lane offsets (bytes)
    const uint32_t a_lane_off = (uint32_t)(((lane & 15) * SA_S + ((lane >> 4) << 3)) * 2);
    const uint32_t b_lane_off = (uint32_t)(((((lane >> 4) << 3) + (lane & 7)) * SA_S
                                            + (((lane >> 3) & 1) << 3)) * 2);

    // async tile loader: 512 16B-chunks per matrix, 128 threads => 4+4 each
    auto load_tile = [&](int kt, int p) {
        const __half* asrc = keys_h + (size_t)m0 * ND + (size_t)kt * T_K;
        const __half* bsrc = ua_h + (size_t)n0 * ND + (size_t)kt * T_K;
        uint32_t ad = sA + p * STAGE_B;
        uint32_t bd = sB + p * STAGE_B;
        #pragma unroll
        for (int i = 0; i < 4; i++) {
            int c0 = tid + i * 128;
            int row = c0 >> 2, ch = c0 & 3;
            uint32_t off = (uint32_t)((row * SA_S + ch * 8) * 2);
            asm volatile("cp.async.cg.shared.global [%0], [%1], 16;"
                :: "r"(ad + off), "l"(asrc + (size_t)row * ND + ch * 8));
            asm volatile("cp.async.cg.shared.global [%0], [%1], 16;"
                :: "r"(bd + off), "l"(bsrc + (size_t)row * ND + ch * 8));
        }
        asm volatile("cp.async.commit_group;");
    };

    load_tile(0, 0);
    load_tile(1, 1);
    load_tile(2, 2);

    for (int j = tid; j < T_N; j += 128) {
        qw_s[j] = g_qw[b * ND + n0 + j];
        va_s[j] = Va_w[n0 + j];
    }

    float acc[4][8][4];
    #pragma unroll
    for (int im = 0; im < 4; im++)
        #pragma unroll
        for (int in = 0; in < 8; in++)
            #pragma unroll
            for (int k = 0; k < 4; k++) acc[im][in][k] = 0.f;

    int p = 0;
    for (int kt = 0; kt < NKT; kt++) {
        if (kt + 2 < NKT)      { asm volatile("cp.async.wait_group 2;"); }
        else if (kt + 1 < NKT) { asm volatile("cp.async.wait_group 1;"); }
        else                   { asm volatile("cp.async.wait_group 0;"); }
        __syncthreads();      // prev compute on recycled stage done + tile kt visible
        if (kt + 3 < NKT) {
            int pn = p + 3; if (pn >= NSTAGE) pn -= NSTAGE;
            load_tile(kt + 3, pn);
        }

        const uint32_t ap = sA + p * STAGE_B + wm * (64 * SA_S * 2) + a_lane_off;
        const uint32_t bp = sB + p * STAGE_B + wn * (64 * SA_S * 2) + b_lane_off;
        #pragma unroll
        for (int ks = 0; ks < 2; ks++) {
            const uint32_t ko = ks * 32;      // 16 halves
            uint32_t afr[4][4], bfr[4][4];
            #pragma unroll
            for (int im = 0; im < 4; im++)
                ldsm_x4(afr[im], ap + im * (16 * SA_S * 2) + ko);
            #pragma unroll
            for (int ip = 0; ip < 4; ip++)
                ldsm_x4(bfr[ip], bp + ip * (16 * SA_S * 2) + ko);
            #pragma unroll
            for (int in = 0; in < 8; in++) {
                const uint32_t* bb = &bfr[in >> 1][(in & 1) * 2];
                #pragma unroll
                for (int im = 0; im < 4; im++)
                    mma_f16(acc[im][in], afr[im], bb);
            }
        }
        p++; if (p == NSTAGE) p = 0;
    }

    // Epilogue: score_part[m] = sum_n Va[n] * tanh(acc[m][n] + qw[n]) over this CTA's 128 n
    #pragma unroll
    for (int im = 0; im < 4; im++) {
        float rs0 = 0.f, rs1 = 0.f;
        #pragma unroll
        for (int in = 0; in < 8; in++) {
            int col0 = wn * 64 + in * 8 + 2 * c;
            float v0 = va_s[col0],     q0 = qw_s[col0];
            float v1 = va_s[col0 + 1], q1 = qw_s[col0 + 1];
            rs0 += v0 * tanhf(acc[im][in][0] + q0) + v1 * tanhf(acc[im][in][1] + q1);
            rs1 += v0 * tanhf(acc[im][in][2] + q0) + v1 * tanhf(acc[im][in][3] + q1);
        }
        // reduce the 4 lanes sharing each row (lane^1, lane^2 stay in the quad)
        rs0 += __shfl_xor_sync(0xffffffffu, rs0, 1);
        rs0 += __shfl_xor_sync(0xffffffffu, rs0, 2);
        rs1 += __shfl_xor_sync(0xffffffffu, rs1, 1);
        rs1 += __shfl_xor_sync(0xffffffffu, rs1, 2);
        if (c == 0) {
            int rowb = wm * 64 + im * 16 + r;
            sc_s[wn * 128 + rowb] = rs0;
            sc_s[wn * 128 + rowb + 8] = rs1;
        }
    }
    __syncthreads();
    g_scores_part[nt][m0 + tid] = sc_s[tid] + sc_s[128 + tid];
}

// ---------------- Kernel 2: softmax over S per batch, writes weights output ----------------
__global__ void softmax_kernel(float* __restrict__ wts) {
    int b = blockIdx.x;
    int tid = threadIdx.x;                    // 256 threads
    __shared__ float red[8];
    float v[8];
    float mx = -1e30f;
    #pragma unroll
    for (int i = 0; i < 8; i++) {
        int s = tid + i * 256;
        float x = 0.f;
        #pragma unroll
        for (int t = 0; t < NT_N; t++) x += g_scores_part[t][b * NS + s];
        v[i] = x;
        mx = fmaxf(mx, x);
    }
    #pragma unroll
    for (int o = 16; o; o >>= 1) mx = fmaxf(mx, __shfl_xor_sync(0xffffffffu, mx, o));
    if ((tid & 31) == 0) red[tid >> 5] = mx;
    __syncthreads();
    float bm = red[0];
    #pragma unroll
    for (int i = 1; i < 8; i++) bm = fmaxf(bm, red[i]);
    __syncthreads();
    float sum = 0.f;
    #pragma unroll
    for (int i = 0; i < 8; i++) { v[i] = __expf(v[i] - bm); sum += v[i]; }
    #pragma unroll
    for (int o = 16; o; o >>= 1) sum += __shfl_xor_sync(0xffffffffu, sum, o);
    if ((tid & 31) == 0) red[tid >> 5] = sum;
    __syncthreads();
    float bs = 0.f;
    #pragma unroll
    for (int i = 0; i < 8; i++) bs += red[i];
    float inv = 1.0f / bs;
    #pragma unroll
    for (int i = 0; i < 8; i++) wts[b * NS + tid + i * 256] = v[i] * inv;
}

// ---------------- Kernel 3: context partials (s-split for bandwidth) ----------------
__global__ void ctx_part_kernel(const float* __restrict__ keys, const float* __restrict__ wts) {
    int b = blockIdx.x;
    int d = blockIdx.y * 128 + threadIdx.x;
    int z = blockIdx.z;
    int s0 = z * 256;
    __shared__ float ws[256];
    for (int i = threadIdx.x; i < 256; i += 128) ws[i] = wts[b * NS + s0 + i];
    __syncthreads();
    const float* kp = keys + ((size_t)(b * NS + s0)) * ND + d;
    float acc = 0.f;
    #pragma unroll 8
    for (int s = 0; s < 256; s++) acc += ws[s] * kp[(size_t)s * ND];
    g_ctx_part[z][b * ND + d] = acc;
}

// ---------------- Kernel 4: reduce context partials -> output ----------------
__global__ void ctx_reduce_kernel(float* __restrict__ ctx) {
    int b = blockIdx.x;
    int d = threadIdx.x;                      // 1024 threads
    float a = 0.f;
    #pragma unroll
    for (int z = 0; z < 8; z++) a += g_ctx_part[z][b * ND + d];
    ctx[b * ND + d] = a;
}

// ---------------- launch ----------------
extern "C" void kernel_launch(void* const* d_in, const int* in_sizes, int n_in,
                              void* d_out, int out_size) {
    const float* query = (const float*)d_in[0];
    const float* keys  = (const float*)d_in[1];
    const float* Wa_w  = (const float*)d_in[2];
    const float* Wa_b  = (const float*)d_in[3];
    const float* Ua_w  = (const float*)d_in[4];
    const float* Ua_b  = (const float*)d_in[5];
    const float* Va_w  = (const float*)d_in[6];
    // Va_b (d_in[7]) cancels in softmax; scores are not an output.

    float* out = (float*)d_out;
    float* ctx = out;                                  // (B,1,2H) = 32768 floats
    float* wts = (out_size >= NB * ND + NB * NS) ? out + NB * ND : out;  // (B,1,S)

    uint4* keys_h4;  cudaGetSymbolAddress((void**)&keys_h4, g_keys_h4);
    uint4* ua_h4;    cudaGetSymbolAddress((void**)&ua_h4, g_ua_h4);

    cudaFuncSetAttribute(gemm_score_kernel, cudaFuncAttributeMaxDynamicSharedMemorySize, SMEM_BYTES);

    cvt_kernel<<<(size_t)BSR * ND / 8 / 256, 256>>>((const float4*)keys, keys_h4);
    cvt_kernel<<<ND * ND / 8 / 256, 256>>>((const float4*)Ua_w, ua_h4);
    qw_kernel<<<dim3(NB, 8), 128>>>(query, Wa_w, Wa_b, Ua_b);
    gemm_score_kernel<<<dim3(NT_N, BSR / T_M), 128, SMEM_BYTES>>>(Va_w);
    softmax_kernel<<<NB, 256>>>(wts);
    ctx_part_kernel<<<dim3(NB, 8, 8), 128>>>(keys, wts);
    ctx_reduce_kernel<<<NB, 1024>>>(ctx);
}

// round 8
// speedup vs baseline: 1.9375x; 1.0170x over previous
#include <cuda_runtime.h>
#include <cuda_fp16.h>
#include <cstdint>
#include <math.h>

// Problem constants
#define NB   32
#define NS   2048
#define ND   1024
#define BSR  65536      // NB*NS rows
#define T_M  128
#define T_N  128
#define T_K  32
#define NKT  32         // ND / T_K
#define NT_N 8          // 1024 / 128 N-tiles

// Device scratch (no dynamic allocation allowed)
__device__ float g_qw[NB * ND];
__device__ float g_scores_part[NT_N][BSR];
__device__ float g_ctx_part[8][NB * ND];
__device__ uint4 g_keys_h4[(size_t)BSR * ND / 8];   // keys as fp16, 128 MB
__device__ uint4 g_ua_h4[ND * ND / 8];              // Ua_w as fp16, 2 MB

// ---------------- smem layout for gemm kernel (bytes) ----------------
#define SA_S     40                        // halves per row (80B: ldmatrix conflict-free)
#define STAGE_B  (T_M * SA_S * 2)          // 10240 bytes per stage per matrix
#define NSTAGE   4
#define OFF_A    0                         // 4 stages: 40960
#define OFF_B    40960                     // 4 stages: 40960
#define OFF_QW   81920                     // 128 floats
#define OFF_VA   82432                     // 128 floats
#define OFF_SC   82944                     // 256 floats
#define SMEM_BYTES 83968

__device__ __forceinline__ void mma_f16(float* d, const uint32_t* a, const uint32_t* b) {
    asm volatile(
        "mma.sync.aligned.m16n8k16.row.col.f32.f16.f16.f32 "
        "{%0,%1,%2,%3}, {%4,%5,%6,%7}, {%8,%9}, {%0,%1,%2,%3};"
        : "+f"(d[0]), "+f"(d[1]), "+f"(d[2]), "+f"(d[3])
        : "r"(a[0]), "r"(a[1]), "r"(a[2]), "r"(a[3]), "r"(b[0]), "r"(b[1]));
}

__device__ __forceinline__ void ldsm_x4(uint32_t* r, uint32_t addr) {
    asm volatile("ldmatrix.sync.aligned.m8n8.x4.shared.b16 {%0,%1,%2,%3}, [%4];"
        : "=r"(r[0]), "=r"(r[1]), "=r"(r[2]), "=r"(r[3]) : "r"(addr));
}

__device__ __forceinline__ uint32_t pack2h(float x, float y) {
    __half2 h = __floats2half2_rn(x, y);
    return *(uint32_t*)&h;
}

// ---------------- Kernel A: fp32 -> fp16 converters ----------------
__global__ void cvt_kernel(const float4* __restrict__ src, uint4* __restrict__ dst) {
    size_t i = (size_t)blockIdx.x * blockDim.x + threadIdx.x;   // one uint4 = 8 halves
    float4 a = src[2 * i];
    float4 b = src[2 * i + 1];
    uint4 u;
    u.x = pack2h(a.x, a.y);
    u.y = pack2h(a.z, a.w);
    u.z = pack2h(b.x, b.y);
    u.w = pack2h(b.z, b.w);
    dst[i] = u;
}

// ---------------- Kernel 0: qW[b,n] = q[b] . Wa_w[n,:] + Wa_b[n] + Ua_b[n] ----------------
__global__ void qw_kernel(const float* __restrict__ query, const float* __restrict__ Wa_w,
                          const float* __restrict__ Wa_b, const float* __restrict__ Ua_b) {
    int b = blockIdx.x;
    int tid = threadIdx.x;                    // 128 threads
    int n = blockIdx.y * 128 + tid;
    __shared__ float4 qs[256];                // q[b] as 1024 floats
    for (int i = tid; i < 256; i += 128) {
        int k = i * 4;
        // q = concat(query[b,1,:], query[b,3,:]); query is (B,4,512)
        const float* src = (k < 512) ? (query + (size_t)b * 2048 + 512 + k)
                                     : (query + (size_t)b * 2048 + 1024 + k);
        qs[i] = *(const float4*)src;
    }
    __syncthreads();
    const float4* wr = (const float4*)(Wa_w + (size_t)n * ND);
    float acc = 0.f;
    #pragma unroll 8
    for (int i = 0; i < 256; i++) {
        float4 a = qs[i], w = wr[i];
        acc += a.x * w.x + a.y * w.y + a.z * w.z + a.w * w.w;
    }
    g_qw[b * ND + n] = acc + Wa_b[n] + Ua_b[n];
}

// ---------------- Kernel 1: fp16 mma GEMM (128x128 CTA, 4 warps of 64x64, 2 CTA/SM) ----------------
__global__ void __launch_bounds__(128, 2)
gemm_score_kernel(const float* __restrict__ Va_w) {
    extern __shared__ __align__(16) char smc[];
    float* qw_s = (float*)(smc + OFF_QW);
    float* va_s = (float*)(smc + OFF_VA);
    float* sc_s = (float*)(smc + OFF_SC);

    const __half* keys_h = (const __half*)g_keys_h4;
    const __half* ua_h   = (const __half*)g_ua_h4;

    const int tid = threadIdx.x;              // 128 threads, 4 warps
    const int wid = tid >> 5;
    const int lane = tid & 31;
    const int r = lane >> 2;                  // 0..7
    const int c = lane & 3;                   // 0..3
    const int wm = wid & 1;                   // 2 warps along M (64 rows each)
    const int wn = wid >> 1;                  // 2 warps along N (64 cols each)

    const int nt = blockIdx.x;                // N-tile (fast dim -> A reuse in L2)
    const int n0 = nt * T_N;
    const int m0 = blockIdx.y * T_M;
    const int b  = blockIdx.y >> 4;           // 16 M-tiles of 128 per batch

    const uint32_t sbase = (uint32_t)__cvta_generic_to_shared(smc);
    const uint32_t sA = sbase + OFF_A;
    const uint32_t sB = sbase + OFF_B;

    // ldmatrix per-lane offsets (bytes)
    const uint32_t a_lane_off = (uint32_t)(((lane & 15) * SA_S + ((lane >> 4) << 3)) * 2);
    const uint32_t b_lane_off = (uint32_t)(((((lane >> 4) << 3) + (lane & 7)) * SA_S
                                            + (((lane >> 3) & 1) << 3)) * 2);

    // async tile loader: 512 16B-chunks per matrix, 128 threads => 4+4 each
    auto load_tile = [&](int kt, int p) {
        const __half* asrc = keys_h + (size_t)m0 * ND + (size_t)kt * T_K;
        const __half* bsrc = ua_h + (size_t)n0 * ND + (size_t)kt * T_K;
        uint32_t ad = sA + p * STAGE_B;
        uint32_t bd = sB + p * STAGE_B;
        #pragma unroll
        for (int i = 0; i < 4; i++) {
            int c0 = tid + i * 128;
            int row = c0 >> 2, ch = c0 & 3;
            uint32_t off = (uint32_t)((row * SA_S + ch * 8) * 2);
            asm volatile("cp.async.cg.shared.global [%0], [%1], 16;"
                :: "r"(ad + off), "l"(asrc + (size_t)row * ND + ch * 8));
            asm volatile("cp.async.cg.shared.global [%0], [%1], 16;"
                :: "r"(bd + off), "l"(bsrc + (size_t)row * ND + ch * 8));
        }
        asm volatile("cp.async.commit_group;");
    };

    load_tile(0, 0);
    load_tile(1, 1);
    load_tile(2, 2);

    for (int j = tid; j < T_N; j += 128) {
        qw_s[j] = g_qw[b * ND + n0 + j];
        va_s[j] = Va_w[n0 + j];
    }

    float acc[4][8][4];
    #pragma unroll
    for (int im = 0; im < 4; im++)
        #pragma unroll
        for (int in = 0; in < 8; in++)
            #pragma unroll
            for (int k = 0; k < 4; k++) acc[im][in][k] = 0.f;

    int p = 0;
    for (int kt = 0; kt < NKT; kt++) {
        if (kt + 2 < NKT)      { asm volatile("cp.async.wait_group 2;"); }
        else if (kt + 1 < NKT) { asm volatile("cp.async.wait_group 1;"); }
        else                   { asm volatile("cp.async.wait_group 0;"); }
        __syncthreads();      // prev compute on recycled stage done + tile kt visible
        if (kt + 3 < NKT) {
            int pn = p + 3; if (pn >= NSTAGE) pn -= NSTAGE;
            load_tile(kt + 3, pn);
        }

        const uint32_t ap = sA + p * STAGE_B + wm * (64 * SA_S * 2) + a_lane_off;
        const uint32_t bp = sB + p * STAGE_B + wn * (64 * SA_S * 2) + b_lane_off;

        // hoist ALL 16 LDSM for this K-tile, then stream 64 uninterrupted MMAs
        uint32_t afr[2][4][4], bfr[2][4][4];
        #pragma unroll
        for (int ks = 0; ks < 2; ks++) {
            const uint32_t ko = ks * 32;      // 16 halves
            #pragma unroll
            for (int im = 0; im < 4; im++)
                ldsm_x4(afr[ks][im], ap + im * (16 * SA_S * 2) + ko);
            #pragma unroll
            for (int ip = 0; ip < 4; ip++)
                ldsm_x4(bfr[ks][ip], bp + ip * (16 * SA_S * 2) + ko);
        }
        #pragma unroll
        for (int ks = 0; ks < 2; ks++) {
            #pragma unroll
            for (int in = 0; in < 8; in++) {
                const uint32_t* bb = &bfr[ks][in >> 1][(in & 1) * 2];
                #pragma unroll
                for (int im = 0; im < 4; im++)
                    mma_f16(acc[im][in], afr[ks][im], bb);
            }
        }
        p++; if (p == NSTAGE) p = 0;
    }

    // Epilogue: score_part[m] = sum_n Va[n] * tanh(acc[m][n] + qw[n]) over this CTA's 128 n
    #pragma unroll
    for (int im = 0; im < 4; im++) {
        float rs0 = 0.f, rs1 = 0.f;
        #pragma unroll
        for (int in = 0; in < 8; in++) {
            int col0 = wn * 64 + in * 8 + 2 * c;
            float v0 = va_s[col0],     q0 = qw_s[col0];
            float v1 = va_s[col0 + 1], q1 = qw_s[col0 + 1];
            rs0 += v0 * tanhf(acc[im][in][0] + q0) + v1 * tanhf(acc[im][in][1] + q1);
            rs1 += v0 * tanhf(acc[im][in][2] + q0) + v1 * tanhf(acc[im][in][3] + q1);
        }
        // reduce the 4 lanes sharing each row (lane^1, lane^2 stay in the quad)
        rs0 += __shfl_xor_sync(0xffffffffu, rs0, 1);
        rs0 += __shfl_xor_sync(0xffffffffu, rs0, 2);
        rs1 += __shfl_xor_sync(0xffffffffu, rs1, 1);
        rs1 += __shfl_xor_sync(0xffffffffu, rs1, 2);
        if (c == 0) {
            int rowb = wm * 64 + im * 16 + r;
            sc_s[wn * 128 + rowb] = rs0;
            sc_s[wn * 128 + rowb + 8] = rs1;
        }
    }
    __syncthreads();
    g_scores_part[nt][m0 + tid] = sc_s[tid] + sc_s[128 + tid];
}

// ---------------- Kernel 2: softmax over S per batch, writes weights output ----------------
__global__ void softmax_kernel(float* __restrict__ wts) {
    int b = blockIdx.x;
    int tid = threadIdx.x;                    // 256 threads
    __shared__ float red[8];
    float v[8];
    float mx = -1e30f;
    #pragma unroll
    for (int i = 0; i < 8; i++) {
        int s = tid + i * 256;
        float x = 0.f;
        #pragma unroll
        for (int t = 0; t < NT_N; t++) x += g_scores_part[t][b * NS + s];
        v[i] = x;
        mx = fmaxf(mx, x);
    }
    #pragma unroll
    for (int o = 16; o; o >>= 1) mx = fmaxf(mx, __shfl_xor_sync(0xffffffffu, mx, o));
    if ((tid & 31) == 0) red[tid >> 5] = mx;
    __syncthreads();
    float bm = red[0];
    #pragma unroll
    for (int i = 1; i < 8; i++) bm = fmaxf(bm, red[i]);
    __syncthreads();
    float sum = 0.f;
    #pragma unroll
    for (int i = 0; i < 8; i++) { v[i] = __expf(v[i] - bm); sum += v[i]; }
    #pragma unroll
    for (int o = 16; o; o >>= 1) sum += __shfl_xor_sync(0xffffffffu, sum, o);
    if ((tid & 31) == 0) red[tid >> 5] = sum;
    __syncthreads();
    float bs = 0.f;
    #pragma unroll
    for (int i = 0; i < 8; i++) bs += red[i];
    float inv = 1.0f / bs;
    #pragma unroll
    for (int i = 0; i < 8; i++) wts[b * NS + tid + i * 256] = v[i] * inv;
}

// ---------------- Kernel 3: context partials from fp16 keys (halved traffic) ----------------
__global__ void ctx_part_kernel(const float* __restrict__ wts) {
    const __half* keys_h = (const __half*)g_keys_h4;
    int b = blockIdx.x;
    int d = blockIdx.y * 128 + threadIdx.x;
    int z = blockIdx.z;
    int s0 = z * 256;
    __shared__ float ws[256];
    for (int i = threadIdx.x; i < 256; i += 128) ws[i] = wts[b * NS + s0 + i];
    __syncthreads();
    const __half* kp = keys_h + ((size_t)(b * NS + s0)) * ND + d;
    float acc = 0.f;
    #pragma unroll 8
    for (int s = 0; s < 256; s++) acc += ws[s] * __half2float(kp[(size_t)s * ND]);
    g_ctx_part[z][b * ND + d] = acc;
}

// ---------------- Kernel 4: reduce context partials -> output ----------------
__global__ void ctx_reduce_kernel(float* __restrict__ ctx) {
    int b = blockIdx.x;
    int d = threadIdx.x;                      // 1024 threads
    float a = 0.f;
    #pragma unroll
    for (int z = 0; z < 8; z++) a += g_ctx_part[z][b * ND + d];
    ctx[b * ND + d] = a;
}

// ---------------- launch ----------------
extern "C" void kernel_launch(void* const* d_in, const int* in_sizes, int n_in,
                              void* d_out, int out_size) {
    const float* query = (const float*)d_in[0];
    const float* keys  = (const float*)d_in[1];
    const float* Wa_w  = (const float*)d_in[2];
    const float* Wa_b  = (const float*)d_in[3];
    const float* Ua_w  = (const float*)d_in[4];
    const float* Ua_b  = (const float*)d_in[5];
    const float* Va_w  = (const float*)d_in[6];
    // Va_b (d_in[7]) cancels in softmax; scores are not an output.

    float* out = (float*)d_out;
    float* ctx = out;                                  // (B,1,2H) = 32768 floats
    float* wts = (out_size >= NB * ND + NB * NS) ? out + NB * ND : out;  // (B,1,S)

    uint4* keys_h4;  cudaGetSymbolAddress((void**)&keys_h4, g_keys_h4);
    uint4* ua_h4;    cudaGetSymbolAddress((void**)&ua_h4, g_ua_h4);

    cudaFuncSetAttribute(gemm_score_kernel, cudaFuncAttributeMaxDynamicSharedMemorySize, SMEM_BYTES);

    cvt_kernel<<<(size_t)BSR * ND / 8 / 256, 256>>>((const float4*)keys, keys_h4);
    cvt_kernel<<<ND * ND / 8 / 256, 256>>>((const float4*)Ua_w, ua_h4);
    qw_kernel<<<dim3(NB, 8), 128>>>(query, Wa_w, Wa_b, Ua_b);
    gemm_score_kernel<<<dim3(NT_N, BSR / T_M), 128, SMEM_BYTES>>>(Va_w);
    softmax_kernel<<<NB, 256>>>(wts);
    ctx_part_kernel<<<dim3(NB, 8, 8), 128>>>(wts);
    ctx_reduce_kernel<<<NB, 1024>>>(ctx);
}